// round 2
// baseline (speedup 1.0000x reference)
#include <cuda_runtime.h>
#include <math.h>

#define L_SEQ   4096
#define D_MODEL 1024
#define N_HEADS 16
#define HEAD_DIM 64
#define P_DIM   128
#define B_SIZE  4
#define M_FULL  (B_SIZE * L_SEQ)   // 16384
#define M_KV    (B_SIZE * P_DIM)   // 512
#define BH      (B_SIZE * N_HEADS) // 64

// ---------------- scratch (static device arrays; no runtime allocation) ----
__device__ float g_Q   [(size_t)M_FULL * D_MODEL];   // roped Q, [b*L+l, h*64+d]
__device__ float g_K   [(size_t)M_KV   * D_MODEL];   // roped K (first 128 rows/batch)
__device__ float g_V   [(size_t)M_KV   * D_MODEL];
__device__ float g_KpT [BH * HEAD_DIM * P_DIM];      // [bh][d][p]
__device__ float g_Vp  [BH * P_DIM * HEAD_DIM];      // [bh][p][d]
__device__ float g_attn[(size_t)M_FULL * D_MODEL];   // pre-Wo attention out

// Buffer selectors so kernels reference __device__ globals directly
// (no cudaGetSymbolAddress in kernel_launch).
#define BUF_Q    0
#define BUF_K    1
#define BUF_V    2
#define BUF_ATTN 3
#define BUF_EXT  4   // external pointer (harness d_out / d_in)

__device__ __forceinline__ float* buf_ptr(int sel, float* ext) {
    switch (sel) {
        case BUF_Q:    return g_Q;
        case BUF_K:    return g_K;
        case BUF_V:    return g_V;
        case BUF_ATTN: return g_attn;
        default:       return ext;
    }
}

// ---------------------------------------------------------------------------
// NT GEMM: C[m,n] = sum_k A[row(m),k] * B[n,k], K = N = 1024, fp32.
// BM=BN=128, BK=16, 256 threads, 8x8 per thread.
// ROPE: apply interleaved rotary in epilogue (pairs = adjacent columns).
// GATHER: row(m) = (m>>7)*L_SEQ + (m&127)  (first-128-rows-per-batch view of x)
// ASRC/CDST: buffer selectors (compile-time) for A and C.
// ---------------------------------------------------------------------------
template<int ROPE, int GATHER, int ASRC, int CDST>
__global__ void __launch_bounds__(256)
gemm_nt(const float* __restrict__ Aext, const float* __restrict__ Bw,
        float* __restrict__ Cext,
        const float* __restrict__ fcos, const float* __restrict__ fsin,
        int posmask)
{
    const float* A = (ASRC == BUF_EXT) ? Aext : buf_ptr(ASRC, nullptr);
    float*       C = (CDST == BUF_EXT) ? Cext : buf_ptr(CDST, nullptr);

    const int K = 1024, N = 1024;
    __shared__ float As[16][128];
    __shared__ float Bs[16][128];

    const int tid = threadIdx.x;
    const int tx  = tid & 15;
    const int ty  = tid >> 4;
    const int m_tile = blockIdx.y * 128;
    const int n_tile = blockIdx.x * 128;

    float acc[8][8];
#pragma unroll
    for (int i = 0; i < 8; i++)
#pragma unroll
        for (int j = 0; j < 8; j++) acc[i][j] = 0.f;

    const int id0 = tid * 2;

    for (int k0 = 0; k0 < K; k0 += 16) {
#pragma unroll
        for (int t = 0; t < 2; t++) {
            int id = id0 + t;
            int r  = id >> 2;
            int c4 = (id & 3) * 4;
            int m  = m_tile + r;
            int arow = GATHER ? ((m >> 7) * L_SEQ + (m & 127)) : m;
            float4 va = *(const float4*)(A  + (size_t)arow * K + k0 + c4);
            As[c4+0][r] = va.x; As[c4+1][r] = va.y;
            As[c4+2][r] = va.z; As[c4+3][r] = va.w;
            int n = n_tile + r;
            float4 vb = *(const float4*)(Bw + (size_t)n * K + k0 + c4);
            Bs[c4+0][r] = vb.x; Bs[c4+1][r] = vb.y;
            Bs[c4+2][r] = vb.z; Bs[c4+3][r] = vb.w;
        }
        __syncthreads();
#pragma unroll
        for (int kk = 0; kk < 16; kk++) {
            float4 a0 = *(const float4*)&As[kk][ty * 8];
            float4 a1 = *(const float4*)&As[kk][ty * 8 + 4];
            float4 b0 = *(const float4*)&Bs[kk][tx * 8];
            float4 b1 = *(const float4*)&Bs[kk][tx * 8 + 4];
            float ra[8] = {a0.x,a0.y,a0.z,a0.w,a1.x,a1.y,a1.z,a1.w};
            float rb[8] = {b0.x,b0.y,b0.z,b0.w,b1.x,b1.y,b1.z,b1.w};
#pragma unroll
            for (int i = 0; i < 8; i++)
#pragma unroll
                for (int j = 0; j < 8; j++)
                    acc[i][j] = fmaf(ra[i], rb[j], acc[i][j]);
        }
        __syncthreads();
    }

    const int n_base = n_tile + tx * 8;
#pragma unroll
    for (int i = 0; i < 8; i++) {
        int m = m_tile + ty * 8 + i;
        float outv[8];
        if (ROPE) {
            int pos   = m & posmask;                 // position within sequence
            int jbase = (n_base & 63) >> 1;          // rotary pair index of col 0
#pragma unroll
            for (int jp = 0; jp < 4; jp++) {
                float c = fcos[pos * 32 + jbase + jp];
                float s = fsin[pos * 32 + jbase + jp];
                float v0 = acc[i][jp * 2];
                float v1 = acc[i][jp * 2 + 1];
                outv[jp * 2]     = v0 * c - v1 * s;
                outv[jp * 2 + 1] = v0 * s + v1 * c;
            }
        } else {
#pragma unroll
            for (int j = 0; j < 8; j++) outv[j] = acc[i][j];
        }
        *(float4*)(C + (size_t)m * N + n_base)     = make_float4(outv[0],outv[1],outv[2],outv[3]);
        *(float4*)(C + (size_t)m * N + n_base + 4) = make_float4(outv[4],outv[5],outv[6],outv[7]);
    }
}

// ---------------------------------------------------------------------------
// K_proj / V_proj: per (b,h):  out[p,d] = sum_{l<=p} proj[p,l] * X[b, l, h*64+d]
// (tril structure: only l <= p <= 127 contributes)
// KpT stored transposed [d][p] for conflict-free attention reads; Vp natural.
// ---------------------------------------------------------------------------
__global__ void __launch_bounds__(256)
proj_kernel(const float* __restrict__ kpm, const float* __restrict__ vpm)
{
    __shared__ float Ts[128][65];
    const int bh = blockIdx.x;
    const int b  = bh >> 4;
    const int h  = bh & 15;
    const int tid = threadIdx.x;

    // ---- K ----
    for (int idx = tid; idx < 128 * 64; idx += 256) {
        int l = idx >> 6, d = idx & 63;
        Ts[l][d] = g_K[(size_t)(b * 128 + l) * 1024 + h * 64 + d];
    }
    __syncthreads();
    for (int o = tid; o < 128 * 64; o += 256) {
        int p = o >> 6, d = o & 63;
        const float* pr = kpm + (size_t)p * 4096;
        float s = 0.f;
        for (int l = 0; l <= p; l++) s = fmaf(pr[l], Ts[l][d], s);
        g_KpT[(size_t)bh * 8192 + d * 128 + p] = s;
    }
    __syncthreads();
    // ---- V ----
    for (int idx = tid; idx < 128 * 64; idx += 256) {
        int l = idx >> 6, d = idx & 63;
        Ts[l][d] = g_V[(size_t)(b * 128 + l) * 1024 + h * 64 + d];
    }
    __syncthreads();
    for (int o = tid; o < 128 * 64; o += 256) {
        int p = o >> 6, d = o & 63;
        const float* pr = vpm + (size_t)p * 4096;
        float s = 0.f;
        for (int l = 0; l <= p; l++) s = fmaf(pr[l], Ts[l][d], s);
        g_Vp[(size_t)bh * 8192 + p * 64 + d] = s;
    }
}

// ---------------------------------------------------------------------------
// Fused attention. Grid (L/64, B*H), block 256.
// S = Q_tile @ KpT (64x128), mask p>l, softmax over 128, O = W @ Vp (64x64).
// ---------------------------------------------------------------------------
#define RS 132
#define ATTN_SMEM ((64*64 + 64*128 + 128*64 + 64*RS) * 4)

__global__ void __launch_bounds__(256)
attn_kernel()
{
    extern __shared__ float sm[];
    float* Qs = sm;                 // [64][64]
    float* Ks = Qs + 64 * 64;       // KpT tile [64][128]  (d-major)
    float* Vs = Ks + 64 * 128;      // [128][64]
    float* Ss = Vs + 128 * 64;      // [64][RS]

    const int bh = blockIdx.y;
    const int b  = bh >> 4;
    const int h  = bh & 15;
    const int l0 = blockIdx.x * 64;
    const int tid = threadIdx.x;
    const int tx  = tid & 15;
    const int ty  = tid >> 4;

    // stage tiles
    const float* Qbase = g_Q + ((size_t)(b * L_SEQ + l0)) * 1024 + h * 64;
    for (int i4 = tid; i4 < 64 * 16; i4 += 256) {
        int r = i4 >> 4, c4 = (i4 & 15) * 4;
        *(float4*)(Qs + r * 64 + c4) = *(const float4*)(Qbase + (size_t)r * 1024 + c4);
    }
    const float4* Kb = (const float4*)(g_KpT + (size_t)bh * 8192);
    for (int i4 = tid; i4 < 2048; i4 += 256) ((float4*)Ks)[i4] = Kb[i4];
    const float4* Vb = (const float4*)(g_Vp + (size_t)bh * 8192);
    for (int i4 = tid; i4 < 2048; i4 += 256) ((float4*)Vs)[i4] = Vb[i4];
    __syncthreads();

    // ---- S = Q @ KpT, 4x8 register tile per thread ----
    const int i0 = ty * 4;
    const int p0 = tx * 8;
    float acc[4][8];
#pragma unroll
    for (int i = 0; i < 4; i++)
#pragma unroll
        for (int j = 0; j < 8; j++) acc[i][j] = 0.f;

    for (int d = 0; d < 64; d++) {
        float4 k0 = *(const float4*)(Ks + d * 128 + p0);
        float4 k1 = *(const float4*)(Ks + d * 128 + p0 + 4);
        float kr[8] = {k0.x,k0.y,k0.z,k0.w,k1.x,k1.y,k1.z,k1.w};
#pragma unroll
        for (int ii = 0; ii < 4; ii++) {
            float q = Qs[(i0 + ii) * 64 + d];
#pragma unroll
            for (int j = 0; j < 8; j++)
                acc[ii][j] = fmaf(q, kr[j], acc[ii][j]);
        }
    }
    // scale + causal-vs-P mask + store to smem
#pragma unroll
    for (int ii = 0; ii < 4; ii++) {
        int l = l0 + i0 + ii;
#pragma unroll
        for (int j = 0; j < 8; j++) {
            int p = p0 + j;
            float s = acc[ii][j] * 0.125f;
            if (p > l) s = -1e30f;
            Ss[(i0 + ii) * RS + p] = s;
        }
    }
    __syncthreads();

    // ---- softmax: 8 warps x 8 rows ----
    const int warp = tid >> 5, lane = tid & 31;
    for (int r = warp * 8; r < warp * 8 + 8; r++) {
        float v[4];
#pragma unroll
        for (int k = 0; k < 4; k++) v[k] = Ss[r * RS + lane + 32 * k];
        float mx = fmaxf(fmaxf(v[0], v[1]), fmaxf(v[2], v[3]));
#pragma unroll
        for (int off = 16; off > 0; off >>= 1)
            mx = fmaxf(mx, __shfl_xor_sync(0xffffffffu, mx, off));
        float sum = 0.f;
#pragma unroll
        for (int k = 0; k < 4; k++) { v[k] = __expf(v[k] - mx); sum += v[k]; }
#pragma unroll
        for (int off = 16; off > 0; off >>= 1)
            sum += __shfl_xor_sync(0xffffffffu, sum, off);
        float inv = 1.0f / sum;
#pragma unroll
        for (int k = 0; k < 4; k++) Ss[r * RS + lane + 32 * k] = v[k] * inv;
    }
    __syncthreads();

    // ---- O = W @ Vp, 4x4 register tile per thread ----
    const int d0 = tx * 4;
    float o[4][4];
#pragma unroll
    for (int i = 0; i < 4; i++)
#pragma unroll
        for (int j = 0; j < 4; j++) o[i][j] = 0.f;

    for (int p = 0; p < 128; p++) {
        float4 vv = *(const float4*)(Vs + p * 64 + d0);
#pragma unroll
        for (int ii = 0; ii < 4; ii++) {
            float w = Ss[(i0 + ii) * RS + p];
            o[ii][0] = fmaf(w, vv.x, o[ii][0]);
            o[ii][1] = fmaf(w, vv.y, o[ii][1]);
            o[ii][2] = fmaf(w, vv.z, o[ii][2]);
            o[ii][3] = fmaf(w, vv.w, o[ii][3]);
        }
    }
#pragma unroll
    for (int ii = 0; ii < 4; ii++) {
        size_t row = (size_t)(b * L_SEQ + l0 + i0 + ii);
        *(float4*)(g_attn + row * 1024 + h * 64 + d0) =
            make_float4(o[ii][0], o[ii][1], o[ii][2], o[ii][3]);
    }
}

// ---------------------------------------------------------------------------
extern "C" void kernel_launch(void* const* d_in, const int* in_sizes, int n_in,
                              void* d_out, int out_size)
{
    const float* x    = (const float*)d_in[0];
    const float* fcos = (const float*)d_in[1];
    const float* fsin = (const float*)d_in[2];
    const float* Wq   = (const float*)d_in[3];
    const float* Wk   = (const float*)d_in[4];
    const float* Wv   = (const float*)d_in[5];
    const float* Wo   = (const float*)d_in[6];
    const float* kpm  = (const float*)d_in[7];
    const float* vpm  = (const float*)d_in[8];
    float* out = (float*)d_out;

    cudaFuncSetAttribute(attn_kernel,
                         cudaFuncAttributeMaxDynamicSharedMemorySize, ATTN_SMEM);

    dim3 blk(256);
    // Q = rope(x @ Wq^T), full M=16384
    gemm_nt<1, 0, BUF_EXT, BUF_Q><<<dim3(8, 128), blk>>>(x, Wq, nullptr, fcos, fsin, L_SEQ - 1);
    // K = rope(x[:, :128] @ Wk^T), M=512  (tril kills l>127)
    gemm_nt<1, 1, BUF_EXT, BUF_K><<<dim3(8, 4),   blk>>>(x, Wk, nullptr, fcos, fsin, P_DIM - 1);
    // V = x[:, :128] @ Wv^T, M=512
    gemm_nt<0, 1, BUF_EXT, BUF_V><<<dim3(8, 4),   blk>>>(x, Wv, nullptr, nullptr, nullptr, 0);
    // lower-triangular Linformer projections
    proj_kernel<<<BH, 256>>>(kpm, vpm);
    // fused scores/softmax/out
    attn_kernel<<<dim3(L_SEQ / 64, BH), 256, ATTN_SMEM>>>();
    // final projection: out = attn @ Wo^T
    gemm_nt<0, 0, BUF_ATTN, BUF_EXT><<<dim3(8, 128), blk>>>(nullptr, Wo, out, nullptr, nullptr, 0);
}

// round 3
// speedup vs baseline: 1.7737x; 1.7737x over previous
#include <cuda_runtime.h>
#include <cuda_bf16.h>
#include <math.h>
#include <stdint.h>

#define L_SEQ   4096
#define D_MODEL 1024
#define N_HEADS 16
#define HEAD_DIM 64
#define P_DIM   128
#define B_SIZE  4
#define M_FULL  (B_SIZE * L_SEQ)   // 16384
#define M_KV    (B_SIZE * P_DIM)   // 512
#define BH      (B_SIZE * N_HEADS) // 64

// ---------------- scratch (static device arrays; no runtime allocation) ----
__device__ __nv_bfloat16 g_xh[(size_t)M_FULL * D_MODEL];  // x split hi
__device__ __nv_bfloat16 g_xl[(size_t)M_FULL * D_MODEL];  // x split lo
__device__ __nv_bfloat16 g_wh[4 * (size_t)D_MODEL * D_MODEL]; // Wq,Wk,Wv,Wo hi
__device__ __nv_bfloat16 g_wl[4 * (size_t)D_MODEL * D_MODEL]; // lo
__device__ __nv_bfloat16 g_ah[(size_t)M_FULL * D_MODEL];  // attn out hi
__device__ __nv_bfloat16 g_al[(size_t)M_FULL * D_MODEL];  // attn out lo

__device__ float g_Q  [(size_t)M_FULL * D_MODEL];   // roped Q fp32
__device__ float g_K  [(size_t)M_KV   * D_MODEL];   // roped K (first 128 rows/batch)
__device__ float g_V  [(size_t)M_KV   * D_MODEL];
__device__ float g_KpT[BH * HEAD_DIM * P_DIM];      // [bh][d][p]
__device__ float g_Vp [BH * P_DIM * HEAD_DIM];      // [bh][p][d]

// ---------------------------------------------------------------------------
// fp32 -> bf16 hi/lo split.  dsel: 0 = x buffers, 1 = weight buffers (+off).
// ---------------------------------------------------------------------------
__global__ void __launch_bounds__(256)
convert_split(const float* __restrict__ src, int dsel, size_t off, size_t n4)
{
    __nv_bfloat16* hb = (dsel == 0) ? g_xh : g_wh;
    __nv_bfloat16* lb = (dsel == 0) ? g_xl : g_wl;
    hb += off; lb += off;
    const float4* s4 = (const float4*)src;
    for (size_t i = blockIdx.x * (size_t)blockDim.x + threadIdx.x; i < n4;
         i += (size_t)gridDim.x * blockDim.x) {
        float4 v = s4[i];
        union { __nv_bfloat16 b[4]; uint2 u; } H, L;
        float f[4] = {v.x, v.y, v.z, v.w};
#pragma unroll
        for (int j = 0; j < 4; j++) {
            __nv_bfloat16 h = __float2bfloat16_rn(f[j]);
            H.b[j] = h;
            L.b[j] = __float2bfloat16_rn(f[j] - __bfloat162float(h));
        }
        ((uint2*)hb)[i] = H.u;
        ((uint2*)lb)[i] = L.u;
    }
}

// ---------------------------------------------------------------------------
// mma.sync helpers
// ---------------------------------------------------------------------------
__device__ __forceinline__ uint32_t sptr(const void* p) {
    return (uint32_t)__cvta_generic_to_shared(p);
}
__device__ __forceinline__ void ldm4(uint32_t* r, uint32_t a) {
    asm volatile("ldmatrix.sync.aligned.m8n8.x4.shared.b16 {%0,%1,%2,%3}, [%4];"
                 : "=r"(r[0]), "=r"(r[1]), "=r"(r[2]), "=r"(r[3]) : "r"(a));
}
__device__ __forceinline__ void mma_bf16(float* c, const uint32_t* a, uint32_t b0, uint32_t b1) {
    asm volatile(
        "mma.sync.aligned.m16n8k16.row.col.f32.bf16.bf16.f32 "
        "{%0,%1,%2,%3}, {%4,%5,%6,%7}, {%8,%9}, {%0,%1,%2,%3};"
        : "+f"(c[0]), "+f"(c[1]), "+f"(c[2]), "+f"(c[3])
        : "r"(a[0]), "r"(a[1]), "r"(a[2]), "r"(a[3]), "r"(b0), "r"(b1));
}

// ---------------------------------------------------------------------------
// bf16x3 NT GEMM on tensor cores:  C[m,n] = sum_k A[row(m),k] * W[n,k]
// A = (Ah + Al), W = (Wh + Wl);  C ~= AhWh + AhWl + AlWh   (fp32 accum)
// Block 128x128, BK=32, 256 thr (8 warps, 4x2 of 32x64 warp tiles).
// ROPE: interleaved rotary in epilogue. GATHER: first-128-rows-per-batch view.
// ASEL: 0 = x, 1 = attn.  WOFF: weight slot.  CSEL: 0=g_Q 1=g_K 2=g_V 3=ext.
// ---------------------------------------------------------------------------
#define SPAD 40  // row stride (bf16) for conflict-free ldmatrix

template<int ROPE, int GATHER, int ASEL, int WOFF, int CSEL>
__global__ void __launch_bounds__(256)
gemm_bf16x3(const float* __restrict__ fcos, const float* __restrict__ fsin,
            float* __restrict__ Cext, int posmask)
{
    const __nv_bfloat16* Ah = (ASEL == 0) ? g_xh : g_ah;
    const __nv_bfloat16* Al = (ASEL == 0) ? g_xl : g_al;
    const __nv_bfloat16* Bh = g_wh + (size_t)WOFF * D_MODEL * D_MODEL;
    const __nv_bfloat16* Bl = g_wl + (size_t)WOFF * D_MODEL * D_MODEL;
    float* C = (CSEL == 0) ? g_Q : (CSEL == 1) ? g_K : (CSEL == 2) ? g_V : Cext;

    __shared__ __nv_bfloat16 sAh[128][SPAD], sAl[128][SPAD];
    __shared__ __nv_bfloat16 sBh[128][SPAD], sBl[128][SPAD];

    const int tid  = threadIdx.x;
    const int warp = tid >> 5;
    const int lane = tid & 31;
    const int wm   = warp & 3;        // 0..3 -> m offset
    const int wn   = warp >> 2;       // 0..1 -> n offset
    const int m_tile = blockIdx.y * 128;
    const int n_tile = blockIdx.x * 128;
    const int lr = lane & 15;
    const int lh = lane >> 4;

    float acc[2][8][4];
#pragma unroll
    for (int i = 0; i < 2; i++)
#pragma unroll
        for (int j = 0; j < 8; j++)
#pragma unroll
            for (int q = 0; q < 4; q++) acc[i][j][q] = 0.f;

    for (int k0 = 0; k0 < 1024; k0 += 32) {
        // ---- stage tiles: 4 x (128 rows x 32 bf16) ----
#pragma unroll
        for (int t = 0; t < 4; t++) {
            int lin = tid + t * 256;          // 0..1023
            int r = lin >> 3, c = (lin & 7) * 4;
            int m = m_tile + r;
            int arow = GATHER ? ((m >> 7) * L_SEQ + (m & 127)) : m;
            *(uint2*)&sAh[r][c] = *(const uint2*)(Ah + (size_t)arow * 1024 + k0 + c);
            *(uint2*)&sAl[r][c] = *(const uint2*)(Al + (size_t)arow * 1024 + k0 + c);
            int n = n_tile + r;
            *(uint2*)&sBh[r][c] = *(const uint2*)(Bh + (size_t)n * 1024 + k0 + c);
            *(uint2*)&sBl[r][c] = *(const uint2*)(Bl + (size_t)n * 1024 + k0 + c);
        }
        __syncthreads();

#pragma unroll
        for (int ks = 0; ks < 32; ks += 16) {
            uint32_t afh[2][4], afl[2][4];
#pragma unroll
            for (int mf = 0; mf < 2; mf++) {
                ldm4(afh[mf], sptr(&sAh[wm * 32 + mf * 16 + lr][ks + lh * 8]));
                ldm4(afl[mf], sptr(&sAl[wm * 32 + mf * 16 + lr][ks + lh * 8]));
            }
            uint32_t bfh[4][4], bfl[4][4];
#pragma unroll
            for (int g = 0; g < 4; g++) {
                ldm4(bfh[g], sptr(&sBh[wn * 64 + g * 16 + lr][ks + lh * 8]));
                ldm4(bfl[g], sptr(&sBl[wn * 64 + g * 16 + lr][ks + lh * 8]));
            }
#pragma unroll
            for (int mf = 0; mf < 2; mf++)
#pragma unroll
                for (int g = 0; g < 4; g++) {
                    // n-frag 2g  = {r0, r2};  n-frag 2g+1 = {r1, r3}
                    mma_bf16(acc[mf][2*g],   afh[mf], bfh[g][0], bfh[g][2]);
                    mma_bf16(acc[mf][2*g],   afh[mf], bfl[g][0], bfl[g][2]);
                    mma_bf16(acc[mf][2*g],   afl[mf], bfh[g][0], bfh[g][2]);
                    mma_bf16(acc[mf][2*g+1], afh[mf], bfh[g][1], bfh[g][3]);
                    mma_bf16(acc[mf][2*g+1], afh[mf], bfl[g][1], bfl[g][3]);
                    mma_bf16(acc[mf][2*g+1], afl[mf], bfh[g][1], bfh[g][3]);
                }
        }
        __syncthreads();
    }

    // ---- epilogue: acc lane layout = rows {l/4, l/4+8}, cols (l%4)*2 + {0,1}
    const int qrow = lane >> 2;
    const int qcol = (lane & 3) * 2;
#pragma unroll
    for (int mf = 0; mf < 2; mf++)
#pragma unroll
        for (int nf = 0; nf < 8; nf++) {
            int n = n_tile + wn * 64 + nf * 8 + qcol;
#pragma unroll
            for (int hhalf = 0; hhalf < 2; hhalf++) {
                int m = m_tile + wm * 32 + mf * 16 + qrow + hhalf * 8;
                float v0 = acc[mf][nf][hhalf * 2];
                float v1 = acc[mf][nf][hhalf * 2 + 1];
                float o0 = v0, o1 = v1;
                if (ROPE) {
                    int pos = m & posmask;
                    int j   = (n & 63) >> 1;
                    float c = __ldg(fcos + pos * 32 + j);
                    float s = __ldg(fsin + pos * 32 + j);
                    o0 = v0 * c - v1 * s;
                    o1 = v0 * s + v1 * c;
                }
                *(float2*)(C + (size_t)m * 1024 + n) = make_float2(o0, o1);
            }
        }
}

// ---------------------------------------------------------------------------
// K_proj / V_proj: per (b,h,dgroup):  out[p,d] = sum_{l<=p} proj[p,l]*X[b,l,h*64+d]
// grid (BH, 8) — 8 d-groups of 8 for parallelism.
// ---------------------------------------------------------------------------
__global__ void __launch_bounds__(256)
proj_kernel(const float* __restrict__ kpm, const float* __restrict__ vpm)
{
    __shared__ float Ts[128][9];
    const int bh = blockIdx.x;
    const int b  = bh >> 4;
    const int hh = bh & 15;
    const int d0 = blockIdx.y * 8;
    const int tid = threadIdx.x;

    // ---- K ----
    for (int idx = tid; idx < 128 * 8; idx += 256) {
        int l = idx >> 3, d = idx & 7;
        Ts[l][d] = g_K[(size_t)(b * 128 + l) * 1024 + hh * 64 + d0 + d];
    }
    __syncthreads();
#pragma unroll
    for (int t = 0; t < 4; t++) {
        int o = tid + t * 256;              // 0..1023
        int p = o >> 3, d = o & 7;
        const float* pr = kpm + (size_t)p * 4096;
        float s = 0.f;
        for (int l = 0; l <= p; l++) s = fmaf(pr[l], Ts[l][d], s);
        g_KpT[(size_t)bh * 8192 + (d0 + d) * 128 + p] = s;
    }
    __syncthreads();
    // ---- V ----
    for (int idx = tid; idx < 128 * 8; idx += 256) {
        int l = idx >> 3, d = idx & 7;
        Ts[l][d] = g_V[(size_t)(b * 128 + l) * 1024 + hh * 64 + d0 + d];
    }
    __syncthreads();
#pragma unroll
    for (int t = 0; t < 4; t++) {
        int o = tid + t * 256;
        int p = o >> 3, d = o & 7;
        const float* pr = vpm + (size_t)p * 4096;
        float s = 0.f;
        for (int l = 0; l <= p; l++) s = fmaf(pr[l], Ts[l][d], s);
        g_Vp[(size_t)bh * 8192 + p * 64 + d0 + d] = s;
    }
}

// ---------------------------------------------------------------------------
// Fused attention. Grid (L/64, B*H), block 256.
// S = Q_tile @ KpT (64x128), mask p>l, softmax over 128, O = W @ Vp (64x64).
// Output written directly as bf16 hi/lo (feeds Wo GEMM).
// ---------------------------------------------------------------------------
#define RS 132
#define ATTN_SMEM ((64*64 + 64*128 + 128*64 + 64*RS) * 4)

__global__ void __launch_bounds__(256)
attn_kernel()
{
    extern __shared__ float sm[];
    float* Qs = sm;                 // [64][64]
    float* Ks = Qs + 64 * 64;       // KpT tile [64][128]  (d-major)
    float* Vs = Ks + 64 * 128;      // [128][64]
    float* Ss = Vs + 128 * 64;      // [64][RS]

    const int bh = blockIdx.y;
    const int b  = bh >> 4;
    const int hh = bh & 15;
    const int l0 = blockIdx.x * 64;
    const int tid = threadIdx.x;
    const int tx  = tid & 15;
    const int ty  = tid >> 4;

    const float* Qbase = g_Q + ((size_t)(b * L_SEQ + l0)) * 1024 + hh * 64;
    for (int i4 = tid; i4 < 64 * 16; i4 += 256) {
        int r = i4 >> 4, c4 = (i4 & 15) * 4;
        *(float4*)(Qs + r * 64 + c4) = *(const float4*)(Qbase + (size_t)r * 1024 + c4);
    }
    const float4* Kb = (const float4*)(g_KpT + (size_t)bh * 8192);
    for (int i4 = tid; i4 < 2048; i4 += 256) ((float4*)Ks)[i4] = Kb[i4];
    const float4* Vb = (const float4*)(g_Vp + (size_t)bh * 8192);
    for (int i4 = tid; i4 < 2048; i4 += 256) ((float4*)Vs)[i4] = Vb[i4];
    __syncthreads();

    // ---- S = Q @ KpT, 4x8 per thread ----
    const int i0 = ty * 4;
    const int p0 = tx * 8;
    float acc[4][8];
#pragma unroll
    for (int i = 0; i < 4; i++)
#pragma unroll
        for (int j = 0; j < 8; j++) acc[i][j] = 0.f;

    for (int d = 0; d < 64; d++) {
        float4 k0 = *(const float4*)(Ks + d * 128 + p0);
        float4 k1 = *(const float4*)(Ks + d * 128 + p0 + 4);
        float kr[8] = {k0.x,k0.y,k0.z,k0.w,k1.x,k1.y,k1.z,k1.w};
#pragma unroll
        for (int ii = 0; ii < 4; ii++) {
            float q = Qs[(i0 + ii) * 64 + d];
#pragma unroll
            for (int j = 0; j < 8; j++)
                acc[ii][j] = fmaf(q, kr[j], acc[ii][j]);
        }
    }
#pragma unroll
    for (int ii = 0; ii < 4; ii++) {
        int l = l0 + i0 + ii;
#pragma unroll
        for (int j = 0; j < 8; j++) {
            int p = p0 + j;
            float s = acc[ii][j] * 0.125f;
            if (p > l) s = -1e30f;
            Ss[(i0 + ii) * RS + p] = s;
        }
    }
    __syncthreads();

    // ---- softmax: 8 warps x 8 rows ----
    const int warp = tid >> 5, lane = tid & 31;
    for (int r = warp * 8; r < warp * 8 + 8; r++) {
        float v[4];
#pragma unroll
        for (int k = 0; k < 4; k++) v[k] = Ss[r * RS + lane + 32 * k];
        float mx = fmaxf(fmaxf(v[0], v[1]), fmaxf(v[2], v[3]));
#pragma unroll
        for (int off = 16; off > 0; off >>= 1)
            mx = fmaxf(mx, __shfl_xor_sync(0xffffffffu, mx, off));
        float sum = 0.f;
#pragma unroll
        for (int k = 0; k < 4; k++) { v[k] = __expf(v[k] - mx); sum += v[k]; }
#pragma unroll
        for (int off = 16; off > 0; off >>= 1)
            sum += __shfl_xor_sync(0xffffffffu, sum, off);
        float inv = 1.0f / sum;
#pragma unroll
        for (int k = 0; k < 4; k++) Ss[r * RS + lane + 32 * k] = v[k] * inv;
    }
    __syncthreads();

    // ---- O = W @ Vp, 4x4 per thread; write bf16 hi/lo ----
    const int d0 = tx * 4;
    float o[4][4];
#pragma unroll
    for (int i = 0; i < 4; i++)
#pragma unroll
        for (int j = 0; j < 4; j++) o[i][j] = 0.f;

    for (int p = 0; p < 128; p++) {
        float4 vv = *(const float4*)(Vs + p * 64 + d0);
#pragma unroll
        for (int ii = 0; ii < 4; ii++) {
            float w = Ss[(i0 + ii) * RS + p];
            o[ii][0] = fmaf(w, vv.x, o[ii][0]);
            o[ii][1] = fmaf(w, vv.y, o[ii][1]);
            o[ii][2] = fmaf(w, vv.z, o[ii][2]);
            o[ii][3] = fmaf(w, vv.w, o[ii][3]);
        }
    }
#pragma unroll
    for (int ii = 0; ii < 4; ii++) {
        size_t idx = (size_t)(b * L_SEQ + l0 + i0 + ii) * 1024 + hh * 64 + d0;
        union { __nv_bfloat16 bb[4]; uint2 u; } H, L;
#pragma unroll
        for (int j = 0; j < 4; j++) {
            __nv_bfloat16 hv = __float2bfloat16_rn(o[ii][j]);
            H.bb[j] = hv;
            L.bb[j] = __float2bfloat16_rn(o[ii][j] - __bfloat162float(hv));
        }
        *(uint2*)(g_ah + idx) = H.u;
        *(uint2*)(g_al + idx) = L.u;
    }
}

// ---------------------------------------------------------------------------
extern "C" void kernel_launch(void* const* d_in, const int* in_sizes, int n_in,
                              void* d_out, int out_size)
{
    const float* x    = (const float*)d_in[0];
    const float* fcos = (const float*)d_in[1];
    const float* fsin = (const float*)d_in[2];
    const float* Wq   = (const float*)d_in[3];
    const float* Wk   = (const float*)d_in[4];
    const float* Wv   = (const float*)d_in[5];
    const float* Wo   = (const float*)d_in[6];
    const float* kpm  = (const float*)d_in[7];
    const float* vpm  = (const float*)d_in[8];
    float* out = (float*)d_out;

    cudaFuncSetAttribute(attn_kernel,
                         cudaFuncAttributeMaxDynamicSharedMemorySize, ATTN_SMEM);

    const size_t DD4 = (size_t)D_MODEL * D_MODEL / 4;
    // splits
    convert_split<<<2048, 256>>>(x,  0, 0,                  (size_t)M_FULL * D_MODEL / 4);
    convert_split<<<256,  256>>>(Wq, 1, 0,                  DD4);
    convert_split<<<256,  256>>>(Wk, 1, (size_t)D_MODEL*D_MODEL,   DD4);
    convert_split<<<256,  256>>>(Wv, 1, (size_t)2*D_MODEL*D_MODEL, DD4);
    convert_split<<<256,  256>>>(Wo, 1, (size_t)3*D_MODEL*D_MODEL, DD4);

    dim3 blk(256);
    // Q = rope(x @ Wq^T), full M=16384
    gemm_bf16x3<1, 0, 0, 0, 0><<<dim3(8, 128), blk>>>(fcos, fsin, nullptr, L_SEQ - 1);
    // K = rope(x[:, :128] @ Wk^T), M=512
    gemm_bf16x3<1, 1, 0, 1, 1><<<dim3(8, 4),   blk>>>(fcos, fsin, nullptr, P_DIM - 1);
    // V = x[:, :128] @ Wv^T, M=512
    gemm_bf16x3<0, 1, 0, 2, 2><<<dim3(8, 4),   blk>>>(nullptr, nullptr, nullptr, 0);
    // lower-triangular Linformer projections
    proj_kernel<<<dim3(BH, 8), blk>>>(kpm, vpm);
    // fused scores/softmax/out (writes bf16 hi/lo)
    attn_kernel<<<dim3(L_SEQ / 64, BH), blk, ATTN_SMEM>>>();
    // final projection: out = attn @ Wo^T
    gemm_bf16x3<0, 0, 1, 3, 3><<<dim3(8, 128), blk>>>(nullptr, nullptr, out, 0);
}

// round 5
// speedup vs baseline: 1.9446x; 1.0964x over previous
#include <cuda_runtime.h>
#include <cuda_bf16.h>
#include <math.h>
#include <stdint.h>

#define L_SEQ   4096
#define D_MODEL 1024
#define N_HEADS 16
#define HEAD_DIM 64
#define P_DIM   128
#define B_SIZE  4
#define M_FULL  (B_SIZE * L_SEQ)   // 16384
#define M_KV    (B_SIZE * P_DIM)   // 512
#define BH      (B_SIZE * N_HEADS) // 64

// ---------------- scratch (static device arrays; no runtime allocation) ----
__device__ __nv_bfloat16 g_xh[(size_t)M_FULL * D_MODEL];
__device__ __nv_bfloat16 g_xl[(size_t)M_FULL * D_MODEL];
__device__ __nv_bfloat16 g_wh[4 * (size_t)D_MODEL * D_MODEL];
__device__ __nv_bfloat16 g_wl[4 * (size_t)D_MODEL * D_MODEL];
__device__ __nv_bfloat16 g_ah[(size_t)M_FULL * D_MODEL];
__device__ __nv_bfloat16 g_al[(size_t)M_FULL * D_MODEL];

__device__ float g_Q  [(size_t)M_FULL * D_MODEL];
__device__ float g_K  [(size_t)M_KV   * D_MODEL];
__device__ float g_V  [(size_t)M_KV   * D_MODEL];
__device__ float g_KpT[BH * HEAD_DIM * P_DIM];
__device__ float g_Vp [BH * P_DIM * HEAD_DIM];

// ---------------------------------------------------------------------------
// fp32 -> bf16 hi/lo split.
// ---------------------------------------------------------------------------
__global__ void __launch_bounds__(256)
convert_split(const float* __restrict__ src, int dsel, size_t off, size_t n4)
{
    __nv_bfloat16* hb = (dsel == 0) ? g_xh : g_wh;
    __nv_bfloat16* lb = (dsel == 0) ? g_xl : g_wl;
    hb += off; lb += off;
    const float4* s4 = (const float4*)src;
    for (size_t i = blockIdx.x * (size_t)blockDim.x + threadIdx.x; i < n4;
         i += (size_t)gridDim.x * blockDim.x) {
        float4 v = s4[i];
        union { __nv_bfloat16 b[4]; uint2 u; } H, L;
        float f[4] = {v.x, v.y, v.z, v.w};
#pragma unroll
        for (int j = 0; j < 4; j++) {
            __nv_bfloat16 h = __float2bfloat16_rn(f[j]);
            H.b[j] = h;
            L.b[j] = __float2bfloat16_rn(f[j] - __bfloat162float(h));
        }
        ((uint2*)hb)[i] = H.u;
        ((uint2*)lb)[i] = L.u;
    }
}

// ---------------------------------------------------------------------------
// mma.sync helpers
// ---------------------------------------------------------------------------
__device__ __forceinline__ uint32_t sptr(const void* p) {
    return (uint32_t)__cvta_generic_to_shared(p);
}
__device__ __forceinline__ void ldm4(uint32_t* r, uint32_t a) {
    asm volatile("ldmatrix.sync.aligned.m8n8.x4.shared.b16 {%0,%1,%2,%3}, [%4];"
                 : "=r"(r[0]), "=r"(r[1]), "=r"(r[2]), "=r"(r[3]) : "r"(a));
}
__device__ __forceinline__ void mma_bf16(float* c, const uint32_t* a, uint32_t b0, uint32_t b1) {
    asm volatile(
        "mma.sync.aligned.m16n8k16.row.col.f32.bf16.bf16.f32 "
        "{%0,%1,%2,%3}, {%4,%5,%6,%7}, {%8,%9}, {%0,%1,%2,%3};"
        : "+f"(c[0]), "+f"(c[1]), "+f"(c[2]), "+f"(c[3])
        : "r"(a[0]), "r"(a[1]), "r"(a[2]), "r"(a[3]), "r"(b0), "r"(b1));
}
__device__ __forceinline__ void cpa16(uint32_t s, const void* g) {
    asm volatile("cp.async.ca.shared.global [%0], [%1], 16;" :: "r"(s), "l"(g));
}

// ---------------------------------------------------------------------------
// bf16x3 NT GEMM on tensor cores with 2-stage cp.async pipeline.
// C[m,n] = sum_k A[row(m),k] * W[n,k];  A=(Ah+Al), W=(Wh+Wl)
// Block 128x128, BK=32, 256 thr (8 warps, 4x2 of 32x64 warp tiles).
// ---------------------------------------------------------------------------
#define SPAD    40                       // bf16 row stride (80B, 16B-aligned)
#define GSTRIDE (128 * SPAD)             // elems per matrix buffer
#define SM_GEMM (2 * 4 * GSTRIDE * 2)    // 81920 bytes

template<int ROPE, int GATHER, int ASEL, int WOFF, int CSEL>
__global__ void __launch_bounds__(256)
gemm_bf16x3(const float* __restrict__ fcos, const float* __restrict__ fsin,
            float* __restrict__ Cext, int posmask)
{
    extern __shared__ __nv_bfloat16 sbuf[];

    const __nv_bfloat16* Ah = (ASEL == 0) ? g_xh : g_ah;
    const __nv_bfloat16* Al = (ASEL == 0) ? g_xl : g_al;
    const __nv_bfloat16* Bh = g_wh + (size_t)WOFF * D_MODEL * D_MODEL;
    const __nv_bfloat16* Bl = g_wl + (size_t)WOFF * D_MODEL * D_MODEL;
    float* C = (CSEL == 0) ? g_Q : (CSEL == 1) ? g_K : (CSEL == 2) ? g_V : Cext;
    const __nv_bfloat16* mats[4] = {Ah, Al, Bh, Bl};

    const int tid  = threadIdx.x;
    const int warp = tid >> 5;
    const int lane = tid & 31;
    const int wm   = warp & 3;
    const int wn   = warp >> 2;
    const int m_tile = blockIdx.y * 128;
    const int n_tile = blockIdx.x * 128;
    const int lr = lane & 15;
    const int lh = lane >> 4;

    float acc[2][8][4];
#pragma unroll
    for (int i = 0; i < 2; i++)
#pragma unroll
        for (int j = 0; j < 8; j++)
#pragma unroll
            for (int q = 0; q < 4; q++) acc[i][j][q] = 0.f;

    // stage loader: 4 matrices x 128 rows x 32 cols = 2048 x 16B; 8 per thread
    auto load_chunk = [&](int st, int k0) {
#pragma unroll
        for (int t = 0; t < 8; t++) {
            int idx = tid + t * 256;
            int mtx = idx >> 9;               // 0=AH 1=AL 2=BH 3=BL
            int rem = idx & 511;
            int row = rem >> 2;
            int c16 = rem & 3;                // 16B chunk within 32-col row
            int grow;
            if (mtx < 2) {
                int m = m_tile + row;
                grow = GATHER ? ((m >> 7) * L_SEQ + (m & 127)) : m;
            } else {
                grow = n_tile + row;
            }
            const __nv_bfloat16* g = mats[mtx] + (size_t)grow * 1024 + k0 + c16 * 8;
            uint32_t s = sptr(sbuf + (st * 4 + mtx) * GSTRIDE + row * SPAD + c16 * 8);
            cpa16(s, g);
        }
    };

    load_chunk(0, 0);
    asm volatile("cp.async.commit_group;" ::: "memory");

    for (int i = 0; i < 32; i++) {
        if (i + 1 < 32) {
            load_chunk((i + 1) & 1, (i + 1) * 32);
            asm volatile("cp.async.commit_group;" ::: "memory");
            asm volatile("cp.async.wait_group 1;" ::: "memory");
        } else {
            asm volatile("cp.async.wait_group 0;" ::: "memory");
        }
        __syncthreads();

        const __nv_bfloat16* bAh = sbuf + ((i & 1) * 4 + 0) * GSTRIDE;
        const __nv_bfloat16* bAl = sbuf + ((i & 1) * 4 + 1) * GSTRIDE;
        const __nv_bfloat16* bBh = sbuf + ((i & 1) * 4 + 2) * GSTRIDE;
        const __nv_bfloat16* bBl = sbuf + ((i & 1) * 4 + 3) * GSTRIDE;

#pragma unroll
        for (int ks = 0; ks < 32; ks += 16) {
            uint32_t afh[2][4], afl[2][4];
#pragma unroll
            for (int mf = 0; mf < 2; mf++) {
                ldm4(afh[mf], sptr(bAh + (wm * 32 + mf * 16 + lr) * SPAD + ks + lh * 8));
                ldm4(afl[mf], sptr(bAl + (wm * 32 + mf * 16 + lr) * SPAD + ks + lh * 8));
            }
            uint32_t bfh[4][4], bfl[4][4];
#pragma unroll
            for (int g = 0; g < 4; g++) {
                ldm4(bfh[g], sptr(bBh + (wn * 64 + g * 16 + lr) * SPAD + ks + lh * 8));
                ldm4(bfl[g], sptr(bBl + (wn * 64 + g * 16 + lr) * SPAD + ks + lh * 8));
            }
#pragma unroll
            for (int mf = 0; mf < 2; mf++)
#pragma unroll
                for (int g = 0; g < 4; g++) {
                    mma_bf16(acc[mf][2*g],   afh[mf], bfh[g][0], bfh[g][2]);
                    mma_bf16(acc[mf][2*g],   afh[mf], bfl[g][0], bfl[g][2]);
                    mma_bf16(acc[mf][2*g],   afl[mf], bfh[g][0], bfh[g][2]);
                    mma_bf16(acc[mf][2*g+1], afh[mf], bfh[g][1], bfh[g][3]);
                    mma_bf16(acc[mf][2*g+1], afh[mf], bfl[g][1], bfl[g][3]);
                    mma_bf16(acc[mf][2*g+1], afl[mf], bfh[g][1], bfh[g][3]);
                }
        }
        __syncthreads();
    }

    // ---- epilogue: acc lane layout = rows {l/4, l/4+8}, cols (l%4)*2 + {0,1}
    const int qrow = lane >> 2;
    const int qcol = (lane & 3) * 2;
#pragma unroll
    for (int mf = 0; mf < 2; mf++)
#pragma unroll
        for (int nf = 0; nf < 8; nf++) {
            int n = n_tile + wn * 64 + nf * 8 + qcol;
#pragma unroll
            for (int hhalf = 0; hhalf < 2; hhalf++) {
                int m = m_tile + wm * 32 + mf * 16 + qrow + hhalf * 8;
                float v0 = acc[mf][nf][hhalf * 2];
                float v1 = acc[mf][nf][hhalf * 2 + 1];
                float o0 = v0, o1 = v1;
                if (ROPE) {
                    int pos = m & posmask;
                    int j   = (n & 63) >> 1;
                    float c = __ldg(fcos + pos * 32 + j);
                    float s = __ldg(fsin + pos * 32 + j);
                    o0 = v0 * c - v1 * s;
                    o1 = v0 * s + v1 * c;
                }
                *(float2*)(C + (size_t)m * 1024 + n) = make_float2(o0, o1);
            }
        }
}

// ---------------------------------------------------------------------------
// K_proj / V_proj (tril): grid (BH, 8)
// ---------------------------------------------------------------------------
__global__ void __launch_bounds__(256)
proj_kernel(const float* __restrict__ kpm, const float* __restrict__ vpm)
{
    __shared__ float Ts[128][9];
    const int bh = blockIdx.x;
    const int b  = bh >> 4;
    const int hh = bh & 15;
    const int d0 = blockIdx.y * 8;
    const int tid = threadIdx.x;

    for (int idx = tid; idx < 128 * 8; idx += 256) {
        int l = idx >> 3, d = idx & 7;
        Ts[l][d] = g_K[(size_t)(b * 128 + l) * 1024 + hh * 64 + d0 + d];
    }
    __syncthreads();
#pragma unroll
    for (int t = 0; t < 4; t++) {
        int o = tid + t * 256;
        int p = o >> 3, d = o & 7;
        const float* pr = kpm + (size_t)p * 4096;
        float s = 0.f;
        for (int l = 0; l <= p; l++) s = fmaf(pr[l], Ts[l][d], s);
        g_KpT[(size_t)bh * 8192 + (d0 + d) * 128 + p] = s;
    }
    __syncthreads();
    for (int idx = tid; idx < 128 * 8; idx += 256) {
        int l = idx >> 3, d = idx & 7;
        Ts[l][d] = g_V[(size_t)(b * 128 + l) * 1024 + hh * 64 + d0 + d];
    }
    __syncthreads();
#pragma unroll
    for (int t = 0; t < 4; t++) {
        int o = tid + t * 256;
        int p = o >> 3, d = o & 7;
        const float* pr = vpm + (size_t)p * 4096;
        float s = 0.f;
        for (int l = 0; l <= p; l++) s = fmaf(pr[l], Ts[l][d], s);
        g_Vp[(size_t)bh * 8192 + p * 64 + d0 + d] = s;
    }
}

// ---------------------------------------------------------------------------
// Fused attention (unchanged; passing since R2).
// ---------------------------------------------------------------------------
#define RS 132
#define ATTN_SMEM ((64*64 + 64*128 + 128*64 + 64*RS) * 4)

__global__ void __launch_bounds__(256)
attn_kernel()
{
    extern __shared__ float sm[];
    float* Qs = sm;
    float* Ks = Qs + 64 * 64;
    float* Vs = Ks + 64 * 128;
    float* Ss = Vs + 128 * 64;

    const int bh = blockIdx.y;
    const int b  = bh >> 4;
    const int hh = bh & 15;
    const int l0 = blockIdx.x * 64;
    const int tid = threadIdx.x;
    const int tx  = tid & 15;
    const int ty  = tid >> 4;

    const float* Qbase = g_Q + ((size_t)(b * L_SEQ + l0)) * 1024 + hh * 64;
    for (int i4 = tid; i4 < 64 * 16; i4 += 256) {
        int r = i4 >> 4, c4 = (i4 & 15) * 4;
        *(float4*)(Qs + r * 64 + c4) = *(const float4*)(Qbase + (size_t)r * 1024 + c4);
    }
    const float4* Kb = (const float4*)(g_KpT + (size_t)bh * 8192);
    for (int i4 = tid; i4 < 2048; i4 += 256) ((float4*)Ks)[i4] = Kb[i4];
    const float4* Vb = (const float4*)(g_Vp + (size_t)bh * 8192);
    for (int i4 = tid; i4 < 2048; i4 += 256) ((float4*)Vs)[i4] = Vb[i4];
    __syncthreads();

    const int i0 = ty * 4;
    const int p0 = tx * 8;
    float acc[4][8];
#pragma unroll
    for (int i = 0; i < 4; i++)
#pragma unroll
        for (int j = 0; j < 8; j++) acc[i][j] = 0.f;

    for (int d = 0; d < 64; d++) {
        float4 k0 = *(const float4*)(Ks + d * 128 + p0);
        float4 k1 = *(const float4*)(Ks + d * 128 + p0 + 4);
        float kr[8] = {k0.x,k0.y,k0.z,k0.w,k1.x,k1.y,k1.z,k1.w};
#pragma unroll
        for (int ii = 0; ii < 4; ii++) {
            float q = Qs[(i0 + ii) * 64 + d];
#pragma unroll
            for (int j = 0; j < 8; j++)
                acc[ii][j] = fmaf(q, kr[j], acc[ii][j]);
        }
    }
#pragma unroll
    for (int ii = 0; ii < 4; ii++) {
        int l = l0 + i0 + ii;
#pragma unroll
        for (int j = 0; j < 8; j++) {
            int p = p0 + j;
            float s = acc[ii][j] * 0.125f;
            if (p > l) s = -1e30f;
            Ss[(i0 + ii) * RS + p] = s;
        }
    }
    __syncthreads();

    const int warp = tid >> 5, lane = tid & 31;
    for (int r = warp * 8; r < warp * 8 + 8; r++) {
        float v[4];
#pragma unroll
        for (int k = 0; k < 4; k++) v[k] = Ss[r * RS + lane + 32 * k];
        float mx = fmaxf(fmaxf(v[0], v[1]), fmaxf(v[2], v[3]));
#pragma unroll
        for (int off = 16; off > 0; off >>= 1)
            mx = fmaxf(mx, __shfl_xor_sync(0xffffffffu, mx, off));
        float sum = 0.f;
#pragma unroll
        for (int k = 0; k < 4; k++) { v[k] = __expf(v[k] - mx); sum += v[k]; }
#pragma unroll
        for (int off = 16; off > 0; off >>= 1)
            sum += __shfl_xor_sync(0xffffffffu, sum, off);
        float inv = 1.0f / sum;
#pragma unroll
        for (int k = 0; k < 4; k++) Ss[r * RS + lane + 32 * k] = v[k] * inv;
    }
    __syncthreads();

    const int d0 = tx * 4;
    float o[4][4];
#pragma unroll
    for (int i = 0; i < 4; i++)
#pragma unroll
        for (int j = 0; j < 4; j++) o[i][j] = 0.f;

    for (int p = 0; p < 128; p++) {
        float4 vv = *(const float4*)(Vs + p * 64 + d0);
#pragma unroll
        for (int ii = 0; ii < 4; ii++) {
            float w = Ss[(i0 + ii) * RS + p];
            o[ii][0] = fmaf(w, vv.x, o[ii][0]);
            o[ii][1] = fmaf(w, vv.y, o[ii][1]);
            o[ii][2] = fmaf(w, vv.z, o[ii][2]);
            o[ii][3] = fmaf(w, vv.w, o[ii][3]);
        }
    }
#pragma unroll
    for (int ii = 0; ii < 4; ii++) {
        size_t idx = (size_t)(b * L_SEQ + l0 + i0 + ii) * 1024 + hh * 64 + d0;
        union { __nv_bfloat16 bb[4]; uint2 u; } H, L;
#pragma unroll
        for (int j = 0; j < 4; j++) {
            __nv_bfloat16 hv = __float2bfloat16_rn(o[ii][j]);
            H.bb[j] = hv;
            L.bb[j] = __float2bfloat16_rn(o[ii][j] - __bfloat162float(hv));
        }
        *(uint2*)(g_ah + idx) = H.u;
        *(uint2*)(g_al + idx) = L.u;
    }
}

// ---------------------------------------------------------------------------
extern "C" void kernel_launch(void* const* d_in, const int* in_sizes, int n_in,
                              void* d_out, int out_size)
{
    const float* x    = (const float*)d_in[0];
    const float* fcos = (const float*)d_in[1];
    const float* fsin = (const float*)d_in[2];
    const float* Wq   = (const float*)d_in[3];
    const float* Wk   = (const float*)d_in[4];
    const float* Wv   = (const float*)d_in[5];
    const float* Wo   = (const float*)d_in[6];
    const float* kpm  = (const float*)d_in[7];
    const float* vpm  = (const float*)d_in[8];
    float* out = (float*)d_out;

    cudaFuncSetAttribute(attn_kernel,
                         cudaFuncAttributeMaxDynamicSharedMemorySize, ATTN_SMEM);
    cudaFuncSetAttribute(gemm_bf16x3<1,0,0,0,0>, cudaFuncAttributeMaxDynamicSharedMemorySize, SM_GEMM);
    cudaFuncSetAttribute(gemm_bf16x3<1,1,0,1,1>, cudaFuncAttributeMaxDynamicSharedMemorySize, SM_GEMM);
    cudaFuncSetAttribute(gemm_bf16x3<0,1,0,2,2>, cudaFuncAttributeMaxDynamicSharedMemorySize, SM_GEMM);
    cudaFuncSetAttribute(gemm_bf16x3<0,0,1,3,3>, cudaFuncAttributeMaxDynamicSharedMemorySize, SM_GEMM);

    const size_t DD4 = (size_t)D_MODEL * D_MODEL / 4;
    convert_split<<<2048, 256>>>(x,  0, 0,                  (size_t)M_FULL * D_MODEL / 4);
    convert_split<<<256,  256>>>(Wq, 1, 0,                  DD4);
    convert_split<<<256,  256>>>(Wk, 1, (size_t)D_MODEL*D_MODEL,   DD4);
    convert_split<<<256,  256>>>(Wv, 1, (size_t)2*D_MODEL*D_MODEL, DD4);
    convert_split<<<256,  256>>>(Wo, 1, (size_t)3*D_MODEL*D_MODEL, DD4);

    dim3 blk(256);
    // Q = rope(x @ Wq^T)
    gemm_bf16x3<1,0,0,0,0><<<dim3(8, 128), blk, SM_GEMM>>>(fcos, fsin, nullptr, L_SEQ - 1);
    // K = rope(x[:,:128] @ Wk^T)
    gemm_bf16x3<1,1,0,1,1><<<dim3(8, 4),   blk, SM_GEMM>>>(fcos, fsin, nullptr, P_DIM - 1);
    // V = x[:,:128] @ Wv^T
    gemm_bf16x3<0,1,0,2,2><<<dim3(8, 4),   blk, SM_GEMM>>>(nullptr, nullptr, nullptr, 0);
    // Linformer tril projections
    proj_kernel<<<dim3(BH, 8), blk>>>(kpm, vpm);
    // fused attention
    attn_kernel<<<dim3(L_SEQ / 64, BH), blk, ATTN_SMEM>>>();
    // out = attn @ Wo^T
    gemm_bf16x3<0,0,1,3,3><<<dim3(8, 128), blk, SM_GEMM>>>(nullptr, nullptr, out, 0);
}

// round 6
// speedup vs baseline: 2.4751x; 1.2728x over previous
#include <cuda_runtime.h>
#include <cuda_bf16.h>
#include <math.h>
#include <stdint.h>

#define L_SEQ   4096
#define D_MODEL 1024
#define N_HEADS 16
#define HEAD_DIM 64
#define P_DIM   128
#define B_SIZE  4
#define M_FULL  (B_SIZE * L_SEQ)   // 16384
#define M_KV    (B_SIZE * P_DIM)   // 512
#define BH      (B_SIZE * N_HEADS) // 64

// ---------------- scratch (static device arrays) ---------------------------
__device__ __nv_bfloat16 g_xh[(size_t)M_FULL * D_MODEL];
__device__ __nv_bfloat16 g_xl[(size_t)M_FULL * D_MODEL];
__device__ __nv_bfloat16 g_wh[4 * (size_t)D_MODEL * D_MODEL];
__device__ __nv_bfloat16 g_wl[4 * (size_t)D_MODEL * D_MODEL];
__device__ __nv_bfloat16 g_ah[(size_t)M_FULL * D_MODEL];   // attn out hi
__device__ __nv_bfloat16 g_al[(size_t)M_FULL * D_MODEL];   // attn out lo
__device__ __nv_bfloat16 g_qh[(size_t)M_FULL * D_MODEL];   // roped Q hi
__device__ __nv_bfloat16 g_ql[(size_t)M_FULL * D_MODEL];   // roped Q lo

__device__ float g_K[(size_t)M_KV * D_MODEL];
__device__ float g_V[(size_t)M_KV * D_MODEL];

__device__ __nv_bfloat16 g_kph[BH * P_DIM * HEAD_DIM];     // K_proj [bh][p][d] hi
__device__ __nv_bfloat16 g_kpl[BH * P_DIM * HEAD_DIM];
__device__ __nv_bfloat16 g_vth[BH * HEAD_DIM * P_DIM];     // V_proj^T [bh][d][p] hi
__device__ __nv_bfloat16 g_vtl[BH * HEAD_DIM * P_DIM];

// ---------------------------------------------------------------------------
// fp32 -> bf16 hi/lo split.
// ---------------------------------------------------------------------------
__global__ void __launch_bounds__(256)
convert_split(const float* __restrict__ src, int dsel, size_t off, size_t n4)
{
    __nv_bfloat16* hb = (dsel == 0) ? g_xh : g_wh;
    __nv_bfloat16* lb = (dsel == 0) ? g_xl : g_wl;
    hb += off; lb += off;
    const float4* s4 = (const float4*)src;
    for (size_t i = blockIdx.x * (size_t)blockDim.x + threadIdx.x; i < n4;
         i += (size_t)gridDim.x * blockDim.x) {
        float4 v = s4[i];
        union { __nv_bfloat16 b[4]; uint2 u; } H, L;
        float f[4] = {v.x, v.y, v.z, v.w};
#pragma unroll
        for (int j = 0; j < 4; j++) {
            __nv_bfloat16 h = __float2bfloat16_rn(f[j]);
            H.b[j] = h;
            L.b[j] = __float2bfloat16_rn(f[j] - __bfloat162float(h));
        }
        ((uint2*)hb)[i] = H.u;
        ((uint2*)lb)[i] = L.u;
    }
}

// ---------------------------------------------------------------------------
// mma.sync helpers
// ---------------------------------------------------------------------------
__device__ __forceinline__ uint32_t sptr(const void* p) {
    return (uint32_t)__cvta_generic_to_shared(p);
}
__device__ __forceinline__ void ldm4(uint32_t* r, uint32_t a) {
    asm volatile("ldmatrix.sync.aligned.m8n8.x4.shared.b16 {%0,%1,%2,%3}, [%4];"
                 : "=r"(r[0]), "=r"(r[1]), "=r"(r[2]), "=r"(r[3]) : "r"(a));
}
__device__ __forceinline__ void mma_bf16(float* c, const uint32_t* a, uint32_t b0, uint32_t b1) {
    asm volatile(
        "mma.sync.aligned.m16n8k16.row.col.f32.bf16.bf16.f32 "
        "{%0,%1,%2,%3}, {%4,%5,%6,%7}, {%8,%9}, {%0,%1,%2,%3};"
        : "+f"(c[0]), "+f"(c[1]), "+f"(c[2]), "+f"(c[3])
        : "r"(a[0]), "r"(a[1]), "r"(a[2]), "r"(a[3]), "r"(b0), "r"(b1));
}
__device__ __forceinline__ void cpa16(uint32_t s, const void* g) {
    asm volatile("cp.async.ca.shared.global [%0], [%1], 16;" :: "r"(s), "l"(g));
}
__device__ __forceinline__ void split2(float x, float y, uint32_t& h, uint32_t& l) {
    union { __nv_bfloat162 v; uint32_t u; } H, L;
    __nv_bfloat16 xh = __float2bfloat16_rn(x);
    __nv_bfloat16 yh = __float2bfloat16_rn(y);
    H.v = __nv_bfloat162(xh, yh);
    L.v = __nv_bfloat162(__float2bfloat16_rn(x - __bfloat162float(xh)),
                         __float2bfloat16_rn(y - __bfloat162float(yh)));
    h = H.u; l = L.u;
}

// ---------------------------------------------------------------------------
// bf16x3 NT GEMM (from R5, passing). CSEL==0 epilogue writes bf16 hi/lo Q.
// ---------------------------------------------------------------------------
#define SPAD    40
#define GSTRIDE (128 * SPAD)
#define SM_GEMM (2 * 4 * GSTRIDE * 2)    // 81920 bytes

template<int ROPE, int GATHER, int ASEL, int WOFF, int CSEL>
__global__ void __launch_bounds__(256)
gemm_bf16x3(const float* __restrict__ fcos, const float* __restrict__ fsin,
            float* __restrict__ Cext, int posmask)
{
    extern __shared__ __nv_bfloat16 sbuf[];

    const __nv_bfloat16* Ah = (ASEL == 0) ? g_xh : g_ah;
    const __nv_bfloat16* Al = (ASEL == 0) ? g_xl : g_al;
    const __nv_bfloat16* Bh = g_wh + (size_t)WOFF * D_MODEL * D_MODEL;
    const __nv_bfloat16* Bl = g_wl + (size_t)WOFF * D_MODEL * D_MODEL;
    float* C = (CSEL == 1) ? g_K : (CSEL == 2) ? g_V : Cext;
    const __nv_bfloat16* mats[4] = {Ah, Al, Bh, Bl};

    const int tid  = threadIdx.x;
    const int warp = tid >> 5;
    const int lane = tid & 31;
    const int wm   = warp & 3;
    const int wn   = warp >> 2;
    const int m_tile = blockIdx.y * 128;
    const int n_tile = blockIdx.x * 128;
    const int lr = lane & 15;
    const int lh = lane >> 4;

    float acc[2][8][4];
#pragma unroll
    for (int i = 0; i < 2; i++)
#pragma unroll
        for (int j = 0; j < 8; j++)
#pragma unroll
            for (int q = 0; q < 4; q++) acc[i][j][q] = 0.f;

    auto load_chunk = [&](int st, int k0) {
#pragma unroll
        for (int t = 0; t < 8; t++) {
            int idx = tid + t * 256;
            int mtx = idx >> 9;
            int rem = idx & 511;
            int row = rem >> 2;
            int c16 = rem & 3;
            int grow;
            if (mtx < 2) {
                int m = m_tile + row;
                grow = GATHER ? ((m >> 7) * L_SEQ + (m & 127)) : m;
            } else {
                grow = n_tile + row;
            }
            const __nv_bfloat16* g = mats[mtx] + (size_t)grow * 1024 + k0 + c16 * 8;
            uint32_t s = sptr(sbuf + (st * 4 + mtx) * GSTRIDE + row * SPAD + c16 * 8);
            cpa16(s, g);
        }
    };

    load_chunk(0, 0);
    asm volatile("cp.async.commit_group;" ::: "memory");

    for (int i = 0; i < 32; i++) {
        if (i + 1 < 32) {
            load_chunk((i + 1) & 1, (i + 1) * 32);
            asm volatile("cp.async.commit_group;" ::: "memory");
            asm volatile("cp.async.wait_group 1;" ::: "memory");
        } else {
            asm volatile("cp.async.wait_group 0;" ::: "memory");
        }
        __syncthreads();

        const __nv_bfloat16* bAh = sbuf + ((i & 1) * 4 + 0) * GSTRIDE;
        const __nv_bfloat16* bAl = sbuf + ((i & 1) * 4 + 1) * GSTRIDE;
        const __nv_bfloat16* bBh = sbuf + ((i & 1) * 4 + 2) * GSTRIDE;
        const __nv_bfloat16* bBl = sbuf + ((i & 1) * 4 + 3) * GSTRIDE;

#pragma unroll
        for (int ks = 0; ks < 32; ks += 16) {
            uint32_t afh[2][4], afl[2][4];
#pragma unroll
            for (int mf = 0; mf < 2; mf++) {
                ldm4(afh[mf], sptr(bAh + (wm * 32 + mf * 16 + lr) * SPAD + ks + lh * 8));
                ldm4(afl[mf], sptr(bAl + (wm * 32 + mf * 16 + lr) * SPAD + ks + lh * 8));
            }
            uint32_t bfh[4][4], bfl[4][4];
#pragma unroll
            for (int g = 0; g < 4; g++) {
                ldm4(bfh[g], sptr(bBh + (wn * 64 + g * 16 + lr) * SPAD + ks + lh * 8));
                ldm4(bfl[g], sptr(bBl + (wn * 64 + g * 16 + lr) * SPAD + ks + lh * 8));
            }
#pragma unroll
            for (int mf = 0; mf < 2; mf++)
#pragma unroll
                for (int g = 0; g < 4; g++) {
                    mma_bf16(acc[mf][2*g],   afh[mf], bfh[g][0], bfh[g][2]);
                    mma_bf16(acc[mf][2*g],   afh[mf], bfl[g][0], bfl[g][2]);
                    mma_bf16(acc[mf][2*g],   afl[mf], bfh[g][0], bfh[g][2]);
                    mma_bf16(acc[mf][2*g+1], afh[mf], bfh[g][1], bfh[g][3]);
                    mma_bf16(acc[mf][2*g+1], afh[mf], bfl[g][1], bfl[g][3]);
                    mma_bf16(acc[mf][2*g+1], afl[mf], bfh[g][1], bfh[g][3]);
                }
        }
        __syncthreads();
    }

    const int qrow = lane >> 2;
    const int qcol = (lane & 3) * 2;
#pragma unroll
    for (int mf = 0; mf < 2; mf++)
#pragma unroll
        for (int nf = 0; nf < 8; nf++) {
            int n = n_tile + wn * 64 + nf * 8 + qcol;
#pragma unroll
            for (int hhalf = 0; hhalf < 2; hhalf++) {
                int m = m_tile + wm * 32 + mf * 16 + qrow + hhalf * 8;
                float v0 = acc[mf][nf][hhalf * 2];
                float v1 = acc[mf][nf][hhalf * 2 + 1];
                float o0 = v0, o1 = v1;
                if (ROPE) {
                    int pos = m & posmask;
                    int j   = (n & 63) >> 1;
                    float c = __ldg(fcos + pos * 32 + j);
                    float s = __ldg(fsin + pos * 32 + j);
                    o0 = v0 * c - v1 * s;
                    o1 = v0 * s + v1 * c;
                }
                if (CSEL == 0) {
                    uint32_t h, l;
                    split2(o0, o1, h, l);
                    *(uint32_t*)(g_qh + (size_t)m * 1024 + n) = h;
                    *(uint32_t*)(g_ql + (size_t)m * 1024 + n) = l;
                } else {
                    *(float2*)(C + (size_t)m * 1024 + n) = make_float2(o0, o1);
                }
            }
        }
}

// ---------------------------------------------------------------------------
// K_proj / V_proj (tril): grid (BH, 8).  Outputs bf16 hi/lo:
//   Kp  [bh][p][d]   (for S = Q.Kp^T mma, B rows = p, k = d)
//   VpT [bh][d][p]   (for O = W.Vp mma,  B rows = d, k = p)
// ---------------------------------------------------------------------------
__global__ void __launch_bounds__(256)
proj_kernel(const float* __restrict__ kpm, const float* __restrict__ vpm)
{
    __shared__ float Ts[128][9];
    const int bh = blockIdx.x;
    const int b  = bh >> 4;
    const int hh = bh & 15;
    const int d0 = blockIdx.y * 8;
    const int tid = threadIdx.x;

    for (int idx = tid; idx < 128 * 8; idx += 256) {
        int l = idx >> 3, d = idx & 7;
        Ts[l][d] = g_K[(size_t)(b * 128 + l) * 1024 + hh * 64 + d0 + d];
    }
    __syncthreads();
#pragma unroll
    for (int t = 0; t < 4; t++) {
        int o = tid + t * 256;
        int p = o >> 3, d = o & 7;
        const float* pr = kpm + (size_t)p * 4096;
        float s = 0.f;
        for (int l = 0; l <= p; l++) s = fmaf(pr[l], Ts[l][d], s);
        __nv_bfloat16 h = __float2bfloat16_rn(s);
        size_t idx = (size_t)bh * 8192 + p * 64 + (d0 + d);
        g_kph[idx] = h;
        g_kpl[idx] = __float2bfloat16_rn(s - __bfloat162float(h));
    }
    __syncthreads();
    for (int idx = tid; idx < 128 * 8; idx += 256) {
        int l = idx >> 3, d = idx & 7;
        Ts[l][d] = g_V[(size_t)(b * 128 + l) * 1024 + hh * 64 + d0 + d];
    }
    __syncthreads();
#pragma unroll
    for (int t = 0; t < 4; t++) {
        int o = tid + t * 256;
        int p = o >> 3, d = o & 7;
        const float* pr = vpm + (size_t)p * 4096;
        float s = 0.f;
        for (int l = 0; l <= p; l++) s = fmaf(pr[l], Ts[l][d], s);
        __nv_bfloat16 h = __float2bfloat16_rn(s);
        size_t idx = (size_t)bh * 8192 + (d0 + d) * 128 + p;
        g_vth[idx] = h;
        g_vtl[idx] = __float2bfloat16_rn(s - __bfloat162float(h));
    }
}

// ---------------------------------------------------------------------------
// Flash-style mma attention.  Grid (L/128, BH), 256 thr (8 warps x m16 slab).
// S (reg) = Qx3.Kp^T /8, mask, softmax in-reg, W repack -> PVx3 (reg) -> bf16.
// smem: Qh/Ql/Kh/Kl [128][72]b, VTh/VTl [64][136]b  = 108544 B
// ---------------------------------------------------------------------------
#define AT_QH 0
#define AT_QL 18432
#define AT_KH 36864
#define AT_KL 55296
#define AT_VH 73728
#define AT_VL 91136
#define ATTN_SMEM 108544

__global__ void __launch_bounds__(256)
attn_kernel()
{
    extern __shared__ char smem[];
    const int bh = blockIdx.y;
    const int b  = bh >> 4;
    const int hh = bh & 15;
    const int l0 = blockIdx.x * 128;
    const int tid  = threadIdx.x;
    const int wp   = tid >> 5;
    const int lane = tid & 31;
    const int lr   = lane & 15;
    const int lh   = lane >> 4;
    const int qrow = lane >> 2;
    const int qcol = (lane & 3) * 2;

    // ---------------- stage tiles (cp.async) ----------------
    const size_t qbase = (size_t)(b * L_SEQ + l0) * 1024 + hh * 64;
#pragma unroll
    for (int t = 0; t < 4; t++) {
        int i = tid + t * 256;              // 0..1023
        int r = i >> 3, c = i & 7;
        cpa16(sptr(smem + AT_QH + r * 144 + c * 16), g_qh + qbase + (size_t)r * 1024 + c * 8);
        cpa16(sptr(smem + AT_QL + r * 144 + c * 16), g_ql + qbase + (size_t)r * 1024 + c * 8);
        cpa16(sptr(smem + AT_KH + r * 144 + c * 16), g_kph + (size_t)bh * 8192 + r * 64 + c * 8);
        cpa16(sptr(smem + AT_KL + r * 144 + c * 16), g_kpl + (size_t)bh * 8192 + r * 64 + c * 8);
        int rv = i >> 4, cv = i & 15;
        cpa16(sptr(smem + AT_VH + rv * 272 + cv * 16), g_vth + (size_t)bh * 8192 + rv * 128 + cv * 8);
        cpa16(sptr(smem + AT_VL + rv * 272 + cv * 16), g_vtl + (size_t)bh * 8192 + rv * 128 + cv * 8);
    }
    asm volatile("cp.async.commit_group;" ::: "memory");
    asm volatile("cp.async.wait_group 0;" ::: "memory");
    __syncthreads();

    // ---------------- S = Q . Kp^T  (x3), k = d = 64 ----------------
    float acc[16][4];
#pragma unroll
    for (int i = 0; i < 16; i++)
#pragma unroll
        for (int q = 0; q < 4; q++) acc[i][q] = 0.f;

#pragma unroll
    for (int ks = 0; ks < 4; ks++) {
        uint32_t aqh[4], aql[4];
        ldm4(aqh, sptr(smem + AT_QH + (wp * 16 + lr) * 144 + ks * 32 + lh * 16));
        ldm4(aql, sptr(smem + AT_QL + (wp * 16 + lr) * 144 + ks * 32 + lh * 16));
#pragma unroll
        for (int g = 0; g < 8; g++) {
            uint32_t bkh[4], bkl[4];
            ldm4(bkh, sptr(smem + AT_KH + (g * 16 + lr) * 144 + ks * 32 + lh * 16));
            ldm4(bkl, sptr(smem + AT_KL + (g * 16 + lr) * 144 + ks * 32 + lh * 16));
            mma_bf16(acc[2*g],   aqh, bkh[0], bkh[2]);
            mma_bf16(acc[2*g],   aqh, bkl[0], bkl[2]);
            mma_bf16(acc[2*g],   aql, bkh[0], bkh[2]);
            mma_bf16(acc[2*g+1], aqh, bkh[1], bkh[3]);
            mma_bf16(acc[2*g+1], aqh, bkl[1], bkl[3]);
            mma_bf16(acc[2*g+1], aql, bkh[1], bkh[3]);
        }
    }

    // ---------------- scale + mask + softmax (registers) ----------------
#pragma unroll
    for (int i = 0; i < 16; i++)
#pragma unroll
        for (int q = 0; q < 4; q++) acc[i][q] *= 0.125f;

    if (blockIdx.x == 0) {
        const int r0 = wp * 16 + qrow;
        const int r1 = r0 + 8;
#pragma unroll
        for (int nf = 0; nf < 16; nf++) {
            int p0 = nf * 8 + qcol;
            if (p0 > r0)     acc[nf][0] = -1e30f;
            if (p0 + 1 > r0) acc[nf][1] = -1e30f;
            if (p0 > r1)     acc[nf][2] = -1e30f;
            if (p0 + 1 > r1) acc[nf][3] = -1e30f;
        }
    }

    float mx0 = -1e30f, mx1 = -1e30f;
#pragma unroll
    for (int nf = 0; nf < 16; nf++) {
        mx0 = fmaxf(mx0, fmaxf(acc[nf][0], acc[nf][1]));
        mx1 = fmaxf(mx1, fmaxf(acc[nf][2], acc[nf][3]));
    }
    mx0 = fmaxf(mx0, __shfl_xor_sync(0xffffffffu, mx0, 1));
    mx0 = fmaxf(mx0, __shfl_xor_sync(0xffffffffu, mx0, 2));
    mx1 = fmaxf(mx1, __shfl_xor_sync(0xffffffffu, mx1, 1));
    mx1 = fmaxf(mx1, __shfl_xor_sync(0xffffffffu, mx1, 2));

    float s0 = 0.f, s1 = 0.f;
#pragma unroll
    for (int nf = 0; nf < 16; nf++) {
        acc[nf][0] = __expf(acc[nf][0] - mx0);
        acc[nf][1] = __expf(acc[nf][1] - mx0);
        acc[nf][2] = __expf(acc[nf][2] - mx1);
        acc[nf][3] = __expf(acc[nf][3] - mx1);
        s0 += acc[nf][0] + acc[nf][1];
        s1 += acc[nf][2] + acc[nf][3];
    }
    s0 += __shfl_xor_sync(0xffffffffu, s0, 1);
    s0 += __shfl_xor_sync(0xffffffffu, s0, 2);
    s1 += __shfl_xor_sync(0xffffffffu, s1, 1);
    s1 += __shfl_xor_sync(0xffffffffu, s1, 2);
    const float inv0 = 1.0f / s0;
    const float inv1 = 1.0f / s1;

    // ---------------- O = W . Vp  (x3), k = p = 128 ----------------
    float o[8][4];
#pragma unroll
    for (int i = 0; i < 8; i++)
#pragma unroll
        for (int q = 0; q < 4; q++) o[i][q] = 0.f;

#pragma unroll
    for (int kc = 0; kc < 8; kc++) {
        // repack W fragment from acc (C-layout == A-layout trick)
        uint32_t awh[4], awl[4];
        split2(acc[2*kc][0],   acc[2*kc][1],   awh[0], awl[0]);
        split2(acc[2*kc][2],   acc[2*kc][3],   awh[1], awl[1]);
        split2(acc[2*kc+1][0], acc[2*kc+1][1], awh[2], awl[2]);
        split2(acc[2*kc+1][2], acc[2*kc+1][3], awh[3], awl[3]);
#pragma unroll
        for (int g = 0; g < 4; g++) {
            uint32_t bvh[4], bvl[4];
            ldm4(bvh, sptr(smem + AT_VH + (g * 16 + lr) * 272 + kc * 32 + lh * 16));
            ldm4(bvl, sptr(smem + AT_VL + (g * 16 + lr) * 272 + kc * 32 + lh * 16));
            mma_bf16(o[2*g],   awh, bvh[0], bvh[2]);
            mma_bf16(o[2*g],   awh, bvl[0], bvl[2]);
            mma_bf16(o[2*g],   awl, bvh[0], bvh[2]);
            mma_bf16(o[2*g+1], awh, bvh[1], bvh[3]);
            mma_bf16(o[2*g+1], awh, bvl[1], bvl[3]);
            mma_bf16(o[2*g+1], awl, bvh[1], bvh[3]);
        }
    }

    // ---------------- epilogue: normalize + bf16 hi/lo store ----------------
    const size_t row0 = (size_t)(b * L_SEQ + l0 + wp * 16 + qrow);
    const size_t row1 = row0 + 8;
#pragma unroll
    for (int nf = 0; nf < 8; nf++) {
        int col = hh * 64 + nf * 8 + qcol;
        uint32_t h01, l01, h23, l23;
        split2(o[nf][0] * inv0, o[nf][1] * inv0, h01, l01);
        split2(o[nf][2] * inv1, o[nf][3] * inv1, h23, l23);
        *(uint32_t*)(g_ah + row0 * 1024 + col) = h01;
        *(uint32_t*)(g_al + row0 * 1024 + col) = l01;
        *(uint32_t*)(g_ah + row1 * 1024 + col) = h23;
        *(uint32_t*)(g_al + row1 * 1024 + col) = l23;
    }
}

// ---------------------------------------------------------------------------
extern "C" void kernel_launch(void* const* d_in, const int* in_sizes, int n_in,
                              void* d_out, int out_size)
{
    const float* x    = (const float*)d_in[0];
    const float* fcos = (const float*)d_in[1];
    const float* fsin = (const float*)d_in[2];
    const float* Wq   = (const float*)d_in[3];
    const float* Wk   = (const float*)d_in[4];
    const float* Wv   = (const float*)d_in[5];
    const float* Wo   = (const float*)d_in[6];
    const float* kpm  = (const float*)d_in[7];
    const float* vpm  = (const float*)d_in[8];
    float* out = (float*)d_out;

    cudaFuncSetAttribute(attn_kernel,
                         cudaFuncAttributeMaxDynamicSharedMemorySize, ATTN_SMEM);
    cudaFuncSetAttribute(gemm_bf16x3<1,0,0,0,0>, cudaFuncAttributeMaxDynamicSharedMemorySize, SM_GEMM);
    cudaFuncSetAttribute(gemm_bf16x3<1,1,0,1,1>, cudaFuncAttributeMaxDynamicSharedMemorySize, SM_GEMM);
    cudaFuncSetAttribute(gemm_bf16x3<0,1,0,2,2>, cudaFuncAttributeMaxDynamicSharedMemorySize, SM_GEMM);
    cudaFuncSetAttribute(gemm_bf16x3<0,0,1,3,3>, cudaFuncAttributeMaxDynamicSharedMemorySize, SM_GEMM);

    const size_t DD4 = (size_t)D_MODEL * D_MODEL / 4;
    convert_split<<<2048, 256>>>(x,  0, 0,                  (size_t)M_FULL * D_MODEL / 4);
    convert_split<<<256,  256>>>(Wq, 1, 0,                  DD4);
    convert_split<<<256,  256>>>(Wk, 1, (size_t)D_MODEL*D_MODEL,   DD4);
    convert_split<<<256,  256>>>(Wv, 1, (size_t)2*D_MODEL*D_MODEL, DD4);
    convert_split<<<256,  256>>>(Wo, 1, (size_t)3*D_MODEL*D_MODEL, DD4);

    dim3 blk(256);
    // Q = rope(x @ Wq^T) -> bf16 hi/lo
    gemm_bf16x3<1,0,0,0,0><<<dim3(8, 128), blk, SM_GEMM>>>(fcos, fsin, nullptr, L_SEQ - 1);
    // K = rope(x[:,:128] @ Wk^T) fp32
    gemm_bf16x3<1,1,0,1,1><<<dim3(8, 4),   blk, SM_GEMM>>>(fcos, fsin, nullptr, P_DIM - 1);
    // V = x[:,:128] @ Wv^T fp32
    gemm_bf16x3<0,1,0,2,2><<<dim3(8, 4),   blk, SM_GEMM>>>(nullptr, nullptr, nullptr, 0);
    // Linformer tril projections -> bf16 hi/lo (Kp + VpT)
    proj_kernel<<<dim3(BH, 8), blk>>>(kpm, vpm);
    // flash-style mma attention
    attn_kernel<<<dim3(L_SEQ / 128, BH), blk, ATTN_SMEM>>>();
    // out = attn @ Wo^T
    gemm_bf16x3<0,0,1,3,3><<<dim3(8, 128), blk, SM_GEMM>>>(nullptr, nullptr, out, 0);
}